// round 14
// baseline (speedup 1.0000x reference)
#include <cuda_runtime.h>
#include <math.h>

#define Bsz 64
#define Cdim 2048
#define HWs 288
#define NCH 8
#define CCH (Cdim / NCH)   // 256 channels per k_dots block

// Scratch (no allocation allowed; __device__ globals)
__device__ float g_part[Bsz * NCH * 3 * HWs];       // partials, layout (b,ch,j,t)
__device__ float g_invden[Bsz * 2];                 // 1/(sum m + 1e-6)

// ---------------------------------------------------------------------------
// Kernel 1: per-token ||x||^2 + RAW anchor dots (pass 1 over x), float4 loads.
// grid = (B, NCH=8, 2), block = 288.  z splits the 72 quad-columns in half:
// 1024 CTAs (vs 512) for ~2x CTAs/SM with UNCHANGED g_part traffic.
// Anchor normalization deferred to sinkhorn.  First 4 x-loads hoisted above
// the smem-fill barrier.
// ---------------------------------------------------------------------------
__global__ void k_dots(const float* __restrict__ x,
                       const float* __restrict__ anchors) {
    int b  = blockIdx.x;
    int ch = blockIdx.y;
    int z  = blockIdx.z;   // token half
    int t  = threadIdx.x;  // 0..287
    int r8 = t / 36;       // row group 0..7
    int qq = t % 36;       // local quad column
    int q  = z * 36 + qq;  // absolute quad column 0..71

    const float4* xp = (const float4*)(x + ((size_t)b * Cdim + (size_t)ch * CCH) * HWs);

    // Prefetch rows r8, 8+r8, 16+r8, 24+r8 (anchor-independent) BEFORE barrier.
    float4 pf[4];
    #pragma unroll
    for (int l = 0; l < 4; ++l)
        pf[l] = xp[(size_t)(l * 8 + r8) * 72 + q];

    __shared__ float a0s[CCH], a1s[CCH];
    if (t < CCH) {
        a0s[t] = anchors[ch * CCH + t];            // raw (unnormalized)
        a1s[t] = anchors[Cdim + ch * CCH + t];
    }
    __syncthreads();

    float s2[4] = {0,0,0,0}, d0[4] = {0,0,0,0}, d1[4] = {0,0,0,0};

    // consume prefetched iterations i = 0..3
    #pragma unroll
    for (int l = 0; l < 4; ++l) {
        int row = l * 8 + r8;
        float4 v = pf[l];
        float a0 = a0s[row], a1 = a1s[row];
        s2[0] = fmaf(v.x, v.x, s2[0]); d0[0] = fmaf(v.x, a0, d0[0]); d1[0] = fmaf(v.x, a1, d1[0]);
        s2[1] = fmaf(v.y, v.y, s2[1]); d0[1] = fmaf(v.y, a0, d0[1]); d1[1] = fmaf(v.y, a1, d1[1]);
        s2[2] = fmaf(v.z, v.z, s2[2]); d0[2] = fmaf(v.z, a0, d0[2]); d1[2] = fmaf(v.z, a1, d1[2]);
        s2[3] = fmaf(v.w, v.w, s2[3]); d0[3] = fmaf(v.w, a0, d0[3]); d1[3] = fmaf(v.w, a1, d1[3]);
    }

    #pragma unroll 7
    for (int i = 4; i < 32; ++i) {
        int row = i * 8 + r8;
        float4 v = xp[(size_t)row * 72 + q];
        float a0 = a0s[row], a1 = a1s[row];
        s2[0] = fmaf(v.x, v.x, s2[0]); d0[0] = fmaf(v.x, a0, d0[0]); d1[0] = fmaf(v.x, a1, d1[0]);
        s2[1] = fmaf(v.y, v.y, s2[1]); d0[1] = fmaf(v.y, a0, d0[1]); d1[1] = fmaf(v.y, a1, d1[1]);
        s2[2] = fmaf(v.z, v.z, s2[2]); d0[2] = fmaf(v.z, a0, d0[2]); d1[2] = fmaf(v.z, a1, d1[2]);
        s2[3] = fmaf(v.w, v.w, s2[3]); d0[3] = fmaf(v.w, a0, d0[3]); d1[3] = fmaf(v.w, a1, d1[3]);
    }

    // Reduce across the 8 row groups via smem.
    __shared__ float rs[8][36][12];
    float* dst = rs[r8][qq];
    #pragma unroll
    for (int l = 0; l < 4; ++l) { dst[l] = s2[l]; dst[4+l] = d0[l]; dst[8+l] = d1[l]; }
    __syncthreads();

    if (r8 == 0) {
        float acc[12];
        #pragma unroll
        for (int j = 0; j < 12; ++j) {
            float s = 0.f;
            #pragma unroll
            for (int gI = 0; gI < 8; ++gI) s += rs[gI][qq][j];
            acc[j] = s;
        }
        float* gp = g_part + (((size_t)b * NCH + ch) * 3) * HWs;
        #pragma unroll
        for (int j = 0; j < 3; ++j) {
            float4 o = make_float4(acc[4*j+0], acc[4*j+1], acc[4*j+2], acc[4*j+3]);
            *(float4*)(gp + (size_t)j * HWs + q * 4) = o;
        }
    }
}

// ---------------------------------------------------------------------------
// Kernel 2: anchor norms (inline) + reduce partials + 7 sinkhorn iterations,
// emit m and invden.  grid = B, block = 288.
// ---------------------------------------------------------------------------
__global__ void k_sinkhorn(const float* __restrict__ anchors,
                           float* __restrict__ out_m) {
    int b = blockIdx.x;
    int t = threadIdx.x;  // 0..287

    __shared__ float red0[16], red1[16];
    __shared__ float sc0, sc1;

    // ---- anchor inverse norms (L2-hot reads) ----
    {
        float n0 = 0.f, n1 = 0.f;
        for (int c = t; c < Cdim; c += 288) {
            float v = anchors[c];
            float w = anchors[Cdim + c];
            n0 = fmaf(v, v, n0);
            n1 = fmaf(w, w, n1);
        }
        #pragma unroll
        for (int o = 16; o; o >>= 1) {
            n0 += __shfl_down_sync(0xffffffffu, n0, o);
            n1 += __shfl_down_sync(0xffffffffu, n1, o);
        }
        if ((t & 31) == 0) { red0[t >> 5] = n0; red1[t >> 5] = n1; }
        __syncthreads();
        if (t < 32) {
            float q0 = (t < 9) ? red0[t] : 0.f;
            float q1 = (t < 9) ? red1[t] : 0.f;
            #pragma unroll
            for (int o = 8; o; o >>= 1) {
                q0 += __shfl_down_sync(0xffffffffu, q0, o);
                q1 += __shfl_down_sync(0xffffffffu, q1, o);
            }
            if (t == 0) {
                sc0 = 1.f / fmaxf(sqrtf(q0), 1e-12f);
                sc1 = 1.f / fmaxf(sqrtf(q1), 1e-12f);
            }
        }
        __syncthreads();
    }

    float s2 = 0.f, d0 = 0.f, d1 = 0.f;
    #pragma unroll
    for (int ch = 0; ch < NCH; ++ch) {
        const float* p = g_part + (((size_t)b * NCH + ch) * 3) * HWs;
        s2 += p[t];
        d0 += p[HWs + t];
        d1 += p[2 * HWs + t];
    }
    d0 *= sc0;   // deferred anchor normalization
    d1 *= sc1;
    float inorm = 1.f / fmaxf(sqrtf(s2), 1e-12f);
    const float ieps = 1.f / 0.07f;
    float K0 = expf(-(1.f - d0 * inorm) * ieps) + 1e-8f;
    float K1 = expf(-(1.f - d1 * inorm) * ieps) + 1e-8f;

    __shared__ float bc0, bc1;

    float v0 = 1.f, v1 = 1.f, u = 0.f;
    const float a = 1.f / (float)HWs;

    for (int it = 0; it < 7; ++it) {
        float Kv = K0 * v0 + K1 * v1 + 1e-8f;
        u = a / Kv;
        float r0 = K0 * u, r1 = K1 * u;
        #pragma unroll
        for (int o = 16; o; o >>= 1) {
            r0 += __shfl_down_sync(0xffffffffu, r0, o);
            r1 += __shfl_down_sync(0xffffffffu, r1, o);
        }
        if ((t & 31) == 0) { red0[t >> 5] = r0; red1[t >> 5] = r1; }
        __syncthreads();
        if (t < 32) {
            float q0 = (t < 9) ? red0[t] : 0.f;
            float q1 = (t < 9) ? red1[t] : 0.f;
            #pragma unroll
            for (int o = 8; o; o >>= 1) {
                q0 += __shfl_down_sync(0xffffffffu, q0, o);
                q1 += __shfl_down_sync(0xffffffffu, q1, o);
            }
            if (t == 0) { bc0 = 0.5f / (q0 + 1e-8f); bc1 = 0.5f / (q1 + 1e-8f); }
        }
        __syncthreads();
        v0 = bc0; v1 = bc1;
        __syncthreads();
    }

    float m0 = K0 * u * v0 * (float)HWs;
    float m1 = K1 * u * v1 * (float)HWs;
    float* om = out_m + (size_t)b * 2 * HWs;
    om[t]       = m0;
    om[HWs + t] = m1;

    float r0 = m0, r1 = m1;
    #pragma unroll
    for (int o = 16; o; o >>= 1) {
        r0 += __shfl_down_sync(0xffffffffu, r0, o);
        r1 += __shfl_down_sync(0xffffffffu, r1, o);
    }
    if ((t & 31) == 0) { red0[t >> 5] = r0; red1[t >> 5] = r1; }
    __syncthreads();
    if (t < 32) {
        float q0 = (t < 9) ? red0[t] : 0.f;
        float q1 = (t < 9) ? red1[t] : 0.f;
        #pragma unroll
        for (int o = 8; o; o >>= 1) {
            q0 += __shfl_down_sync(0xffffffffu, q0, o);
            q1 += __shfl_down_sync(0xffffffffu, q1, o);
        }
        if (t == 0) {
            g_invden[b * 2 + 0] = 1.f / (q0 + 1e-6f);
            g_invden[b * 2 + 1] = 1.f / (q1 + 1e-6f);
        }
    }
}

// ---------------------------------------------------------------------------
// Kernel 3: masked pooling (pass 2 over x).  grid = (C/64, B), block = 512.
// (R12 version: 27.4us, 71.7% DRAM — unchanged)
// ---------------------------------------------------------------------------
__global__ void k_pool(const float* __restrict__ x,
                       const float* __restrict__ m,
                       float* __restrict__ out) {
    int b  = blockIdx.y;
    int cg = blockIdx.x;
    int tid = threadIdx.x;  // 0..511

    int g = tid >> 3;        // channel within block (0..63)
    int q = tid & 7;         // quad slot (0..7)
    int c = cg * 64 + g;
    const float4* xp = (const float4*)(x + ((size_t)b * Cdim + c) * HWs);

    // 9 independent LDG.128 issued first — overlap the m fill + barrier below.
    float4 xv[9];
    #pragma unroll
    for (int j = 0; j < 9; ++j) xv[j] = xp[q + 8 * j];

    __shared__ float4 msv[144];
    const float4* mg = (const float4*)(m + (size_t)b * 2 * HWs);
    if (tid < 144) msv[tid] = mg[tid];
    __syncthreads();

    float s0a = 0.f, s0b = 0.f, s1a = 0.f, s1b = 0.f;
    #pragma unroll
    for (int j = 0; j < 9; ++j) {
        int i4 = q + 8 * j;
        float4 v  = xv[j];
        float4 w0 = msv[i4];
        float4 w1 = msv[72 + i4];
        s0a = fmaf(v.x, w0.x, s0a); s1a = fmaf(v.x, w1.x, s1a);
        s0b = fmaf(v.y, w0.y, s0b); s1b = fmaf(v.y, w1.y, s1b);
        s0a = fmaf(v.z, w0.z, s0a); s1a = fmaf(v.z, w1.z, s1a);
        s0b = fmaf(v.w, w0.w, s0b); s1b = fmaf(v.w, w1.w, s1b);
    }
    float s0 = s0a + s0b;
    float s1 = s1a + s1b;
    #pragma unroll
    for (int o = 4; o; o >>= 1) {
        s0 += __shfl_down_sync(0xffffffffu, s0, o, 8);
        s1 += __shfl_down_sync(0xffffffffu, s1, o, 8);
    }
    if (q == 0) {
        float i0 = g_invden[b * 2 + 0];
        float i1 = g_invden[b * 2 + 1];
        out[(size_t)b * Cdim + c]                      = s0 * i0;
        out[(size_t)Bsz * Cdim + (size_t)b * Cdim + c] = s1 * i1;
    }
}

// ---------------------------------------------------------------------------
extern "C" void kernel_launch(void* const* d_in, const int* in_sizes, int n_in,
                              void* d_out, int out_size) {
    const float* x       = (const float*)d_in[0];  // (64, 2048, 24, 12)
    const float* anchors = (const float*)d_in[1];  // (2, 2048)
    float* out = (float*)d_out;
    float* out_m = out + (size_t)2 * Bsz * Cdim;

    k_dots<<<dim3(Bsz, NCH, 2), HWs>>>(x, anchors);
    k_sinkhorn<<<Bsz, HWs>>>(anchors, out_m);
    k_pool<<<dim3(Cdim / 64, Bsz), 512>>>(x, out_m, out);
}

// round 15
// speedup vs baseline: 1.0734x; 1.0734x over previous
#include <cuda_runtime.h>
#include <math.h>

#define Bsz 64
#define Cdim 2048
#define HWs 288
#define NCH 8
#define CCH (Cdim / NCH)   // 256 channels per k_dots block

// Scratch (no allocation allowed; __device__ globals)
__device__ float g_part[Bsz * NCH * 3 * HWs];       // partials, layout (b,ch,j,t)
__device__ float g_invden[Bsz * 2];                 // 1/(sum m + 1e-6)

// ---------------------------------------------------------------------------
// Kernel 1: per-token ||x||^2 + RAW anchor dots (pass 1 over x), float4 loads.
// grid = (B, NCH=8), block = 288, __launch_bounds__(288,5): cap regs at ~40
// so 5 CTAs/SM fit (45 warps = 70% occ vs 56% at 42 regs).
// Anchor normalization deferred to sinkhorn.  First 4 x-loads hoisted above
// the smem-fill barrier.
// ---------------------------------------------------------------------------
__global__ void __launch_bounds__(288, 5)
k_dots(const float* __restrict__ x,
       const float* __restrict__ anchors) {
    int b  = blockIdx.x;
    int ch = blockIdx.y;
    int t  = threadIdx.x;  // 0..287
    int r4 = t / 72;
    int q  = t % 72;

    const float4* xp = (const float4*)(x + ((size_t)b * Cdim + (size_t)ch * CCH) * HWs);

    // Prefetch rows r4, 4+r4, 8+r4, 12+r4 (anchor-independent) BEFORE barrier.
    float4 pf[4];
    #pragma unroll
    for (int l = 0; l < 4; ++l)
        pf[l] = xp[(size_t)(l * 4 + r4) * 72 + q];

    __shared__ float a0s[CCH], a1s[CCH];
    if (t < CCH) {
        a0s[t] = anchors[ch * CCH + t];            // raw (unnormalized)
        a1s[t] = anchors[Cdim + ch * CCH + t];
    }
    __syncthreads();

    float s2[4] = {0,0,0,0}, d0[4] = {0,0,0,0}, d1[4] = {0,0,0,0};

    // consume prefetched iterations i = 0..3
    #pragma unroll
    for (int l = 0; l < 4; ++l) {
        int row = l * 4 + r4;
        float4 v = pf[l];
        float a0 = a0s[row], a1 = a1s[row];
        s2[0] = fmaf(v.x, v.x, s2[0]); d0[0] = fmaf(v.x, a0, d0[0]); d1[0] = fmaf(v.x, a1, d1[0]);
        s2[1] = fmaf(v.y, v.y, s2[1]); d0[1] = fmaf(v.y, a0, d0[1]); d1[1] = fmaf(v.y, a1, d1[1]);
        s2[2] = fmaf(v.z, v.z, s2[2]); d0[2] = fmaf(v.z, a0, d0[2]); d1[2] = fmaf(v.z, a1, d1[2]);
        s2[3] = fmaf(v.w, v.w, s2[3]); d0[3] = fmaf(v.w, a0, d0[3]); d1[3] = fmaf(v.w, a1, d1[3]);
    }

    #pragma unroll 8
    for (int i = 4; i < CCH / 4; ++i) {
        int row = i * 4 + r4;
        float4 v = xp[(size_t)row * 72 + q];
        float a0 = a0s[row], a1 = a1s[row];
        s2[0] = fmaf(v.x, v.x, s2[0]); d0[0] = fmaf(v.x, a0, d0[0]); d1[0] = fmaf(v.x, a1, d1[0]);
        s2[1] = fmaf(v.y, v.y, s2[1]); d0[1] = fmaf(v.y, a0, d0[1]); d1[1] = fmaf(v.y, a1, d1[1]);
        s2[2] = fmaf(v.z, v.z, s2[2]); d0[2] = fmaf(v.z, a0, d0[2]); d1[2] = fmaf(v.z, a1, d1[2]);
        s2[3] = fmaf(v.w, v.w, s2[3]); d0[3] = fmaf(v.w, a0, d0[3]); d1[3] = fmaf(v.w, a1, d1[3]);
    }

    __shared__ float rs[4][72][12];
    float* dst = rs[r4][q];
    #pragma unroll
    for (int l = 0; l < 4; ++l) { dst[l] = s2[l]; dst[4+l] = d0[l]; dst[8+l] = d1[l]; }
    __syncthreads();

    if (r4 == 0) {
        float acc[12];
        #pragma unroll
        for (int j = 0; j < 12; ++j)
            acc[j] = rs[0][q][j] + rs[1][q][j] + rs[2][q][j] + rs[3][q][j];
        float* gp = g_part + (((size_t)b * NCH + ch) * 3) * HWs;
        #pragma unroll
        for (int j = 0; j < 3; ++j) {
            float4 o = make_float4(acc[4*j+0], acc[4*j+1], acc[4*j+2], acc[4*j+3]);
            *(float4*)(gp + (size_t)j * HWs + q * 4) = o;
        }
    }
}

// ---------------------------------------------------------------------------
// Kernel 2: anchor norms (inline) + reduce partials + 7 sinkhorn iterations,
// emit m and invden.  grid = B, block = 288.
// ---------------------------------------------------------------------------
__global__ void k_sinkhorn(const float* __restrict__ anchors,
                           float* __restrict__ out_m) {
    int b = blockIdx.x;
    int t = threadIdx.x;  // 0..287

    __shared__ float red0[16], red1[16];
    __shared__ float sc0, sc1;

    // ---- anchor inverse norms (L2-hot reads) ----
    {
        float n0 = 0.f, n1 = 0.f;
        for (int c = t; c < Cdim; c += 288) {
            float v = anchors[c];
            float w = anchors[Cdim + c];
            n0 = fmaf(v, v, n0);
            n1 = fmaf(w, w, n1);
        }
        #pragma unroll
        for (int o = 16; o; o >>= 1) {
            n0 += __shfl_down_sync(0xffffffffu, n0, o);
            n1 += __shfl_down_sync(0xffffffffu, n1, o);
        }
        if ((t & 31) == 0) { red0[t >> 5] = n0; red1[t >> 5] = n1; }
        __syncthreads();
        if (t < 32) {
            float q0 = (t < 9) ? red0[t] : 0.f;
            float q1 = (t < 9) ? red1[t] : 0.f;
            #pragma unroll
            for (int o = 8; o; o >>= 1) {
                q0 += __shfl_down_sync(0xffffffffu, q0, o);
                q1 += __shfl_down_sync(0xffffffffu, q1, o);
            }
            if (t == 0) {
                sc0 = 1.f / fmaxf(sqrtf(q0), 1e-12f);
                sc1 = 1.f / fmaxf(sqrtf(q1), 1e-12f);
            }
        }
        __syncthreads();
    }

    float s2 = 0.f, d0 = 0.f, d1 = 0.f;
    #pragma unroll
    for (int ch = 0; ch < NCH; ++ch) {
        const float* p = g_part + (((size_t)b * NCH + ch) * 3) * HWs;
        s2 += p[t];
        d0 += p[HWs + t];
        d1 += p[2 * HWs + t];
    }
    d0 *= sc0;   // deferred anchor normalization
    d1 *= sc1;
    float inorm = 1.f / fmaxf(sqrtf(s2), 1e-12f);
    const float ieps = 1.f / 0.07f;
    float K0 = expf(-(1.f - d0 * inorm) * ieps) + 1e-8f;
    float K1 = expf(-(1.f - d1 * inorm) * ieps) + 1e-8f;

    __shared__ float bc0, bc1;

    float v0 = 1.f, v1 = 1.f, u = 0.f;
    const float a = 1.f / (float)HWs;

    for (int it = 0; it < 7; ++it) {
        float Kv = K0 * v0 + K1 * v1 + 1e-8f;
        u = a / Kv;
        float r0 = K0 * u, r1 = K1 * u;
        #pragma unroll
        for (int o = 16; o; o >>= 1) {
            r0 += __shfl_down_sync(0xffffffffu, r0, o);
            r1 += __shfl_down_sync(0xffffffffu, r1, o);
        }
        if ((t & 31) == 0) { red0[t >> 5] = r0; red1[t >> 5] = r1; }
        __syncthreads();
        if (t < 32) {
            float q0 = (t < 9) ? red0[t] : 0.f;
            float q1 = (t < 9) ? red1[t] : 0.f;
            #pragma unroll
            for (int o = 8; o; o >>= 1) {
                q0 += __shfl_down_sync(0xffffffffu, q0, o);
                q1 += __shfl_down_sync(0xffffffffu, q1, o);
            }
            if (t == 0) { bc0 = 0.5f / (q0 + 1e-8f); bc1 = 0.5f / (q1 + 1e-8f); }
        }
        __syncthreads();
        v0 = bc0; v1 = bc1;
        __syncthreads();
    }

    float m0 = K0 * u * v0 * (float)HWs;
    float m1 = K1 * u * v1 * (float)HWs;
    float* om = out_m + (size_t)b * 2 * HWs;
    om[t]       = m0;
    om[HWs + t] = m1;

    float r0 = m0, r1 = m1;
    #pragma unroll
    for (int o = 16; o; o >>= 1) {
        r0 += __shfl_down_sync(0xffffffffu, r0, o);
        r1 += __shfl_down_sync(0xffffffffu, r1, o);
    }
    if ((t & 31) == 0) { red0[t >> 5] = r0; red1[t >> 5] = r1; }
    __syncthreads();
    if (t < 32) {
        float q0 = (t < 9) ? red0[t] : 0.f;
        float q1 = (t < 9) ? red1[t] : 0.f;
        #pragma unroll
        for (int o = 8; o; o >>= 1) {
            q0 += __shfl_down_sync(0xffffffffu, q0, o);
            q1 += __shfl_down_sync(0xffffffffu, q1, o);
        }
        if (t == 0) {
            g_invden[b * 2 + 0] = 1.f / (q0 + 1e-6f);
            g_invden[b * 2 + 1] = 1.f / (q1 + 1e-6f);
        }
    }
}

// ---------------------------------------------------------------------------
// Kernel 3: masked pooling (pass 2 over x).  grid = (C/64, B), block = 512.
// (R12 version: 27.4us, 71.7% DRAM — unchanged)
// ---------------------------------------------------------------------------
__global__ void k_pool(const float* __restrict__ x,
                       const float* __restrict__ m,
                       float* __restrict__ out) {
    int b  = blockIdx.y;
    int cg = blockIdx.x;
    int tid = threadIdx.x;  // 0..511

    int g = tid >> 3;        // channel within block (0..63)
    int q = tid & 7;         // quad slot (0..7)
    int c = cg * 64 + g;
    const float4* xp = (const float4*)(x + ((size_t)b * Cdim + c) * HWs);

    // 9 independent LDG.128 issued first — overlap the m fill + barrier below.
    float4 xv[9];
    #pragma unroll
    for (int j = 0; j < 9; ++j) xv[j] = xp[q + 8 * j];

    __shared__ float4 msv[144];
    const float4* mg = (const float4*)(m + (size_t)b * 2 * HWs);
    if (tid < 144) msv[tid] = mg[tid];
    __syncthreads();

    float s0a = 0.f, s0b = 0.f, s1a = 0.f, s1b = 0.f;
    #pragma unroll
    for (int j = 0; j < 9; ++j) {
        int i4 = q + 8 * j;
        float4 v  = xv[j];
        float4 w0 = msv[i4];
        float4 w1 = msv[72 + i4];
        s0a = fmaf(v.x, w0.x, s0a); s1a = fmaf(v.x, w1.x, s1a);
        s0b = fmaf(v.y, w0.y, s0b); s1b = fmaf(v.y, w1.y, s1b);
        s0a = fmaf(v.z, w0.z, s0a); s1a = fmaf(v.z, w1.z, s1a);
        s0b = fmaf(v.w, w0.w, s0b); s1b = fmaf(v.w, w1.w, s1b);
    }
    float s0 = s0a + s0b;
    float s1 = s1a + s1b;
    #pragma unroll
    for (int o = 4; o; o >>= 1) {
        s0 += __shfl_down_sync(0xffffffffu, s0, o, 8);
        s1 += __shfl_down_sync(0xffffffffu, s1, o, 8);
    }
    if (q == 0) {
        float i0 = g_invden[b * 2 + 0];
        float i1 = g_invden[b * 2 + 1];
        out[(size_t)b * Cdim + c]                      = s0 * i0;
        out[(size_t)Bsz * Cdim + (size_t)b * Cdim + c] = s1 * i1;
    }
}

// ---------------------------------------------------------------------------
extern "C" void kernel_launch(void* const* d_in, const int* in_sizes, int n_in,
                              void* d_out, int out_size) {
    const float* x       = (const float*)d_in[0];  // (64, 2048, 24, 12)
    const float* anchors = (const float*)d_in[1];  // (2, 2048)
    float* out = (float*)d_out;
    float* out_m = out + (size_t)2 * Bsz * Cdim;

    k_dots<<<dim3(Bsz, NCH), HWs>>>(x, anchors);
    k_sinkhorn<<<Bsz, HWs>>>(anchors, out_m);
    k_pool<<<dim3(Cdim / 64, Bsz), 512>>>(x, out_m, out);
}

// round 16
// speedup vs baseline: 1.0993x; 1.0241x over previous
#include <cuda_runtime.h>
#include <math.h>

#define Bsz 64
#define Cdim 2048
#define HWs 288
#define NCH 8
#define CCH (Cdim / NCH)   // 256 channels per k_dots block

// Scratch (no allocation allowed; __device__ globals)
__device__ float g_part[Bsz * NCH * 3 * HWs];       // partials, layout (b,ch,j,t)
__device__ float g_invden[Bsz * 2];                 // 1/(sum m + 1e-6)

// ---------------------------------------------------------------------------
// Kernel 1: per-token ||x||^2 + RAW anchor dots (pass 1 over x), float4 loads.
// grid = (B, NCH=8), block = 288.  Anchor normalization deferred to sinkhorn
// (scalar commutes with the dot product).  First 4 x-loads hoisted above the
// smem-fill barrier to hide block-startup latency.       (R13: 29.2us, 67.1%)
// ---------------------------------------------------------------------------
__global__ void k_dots(const float* __restrict__ x,
                       const float* __restrict__ anchors) {
    int b  = blockIdx.x;
    int ch = blockIdx.y;
    int t  = threadIdx.x;  // 0..287
    int r4 = t / 72;
    int q  = t % 72;

    const float4* xp = (const float4*)(x + ((size_t)b * Cdim + (size_t)ch * CCH) * HWs);

    // Prefetch rows r4, 4+r4, 8+r4, 12+r4 (independent of anchors) BEFORE barrier.
    float4 pf[4];
    #pragma unroll
    for (int l = 0; l < 4; ++l)
        pf[l] = xp[(size_t)(l * 4 + r4) * 72 + q];

    __shared__ float a0s[CCH], a1s[CCH];
    if (t < CCH) {
        a0s[t] = anchors[ch * CCH + t];            // raw (unnormalized)
        a1s[t] = anchors[Cdim + ch * CCH + t];
    }
    __syncthreads();

    float s2[4] = {0,0,0,0}, d0[4] = {0,0,0,0}, d1[4] = {0,0,0,0};

    // consume prefetched iterations i = 0..3
    #pragma unroll
    for (int l = 0; l < 4; ++l) {
        int row = l * 4 + r4;
        float4 v = pf[l];
        float a0 = a0s[row], a1 = a1s[row];
        s2[0] = fmaf(v.x, v.x, s2[0]); d0[0] = fmaf(v.x, a0, d0[0]); d1[0] = fmaf(v.x, a1, d1[0]);
        s2[1] = fmaf(v.y, v.y, s2[1]); d0[1] = fmaf(v.y, a0, d0[1]); d1[1] = fmaf(v.y, a1, d1[1]);
        s2[2] = fmaf(v.z, v.z, s2[2]); d0[2] = fmaf(v.z, a0, d0[2]); d1[2] = fmaf(v.z, a1, d1[2]);
        s2[3] = fmaf(v.w, v.w, s2[3]); d0[3] = fmaf(v.w, a0, d0[3]); d1[3] = fmaf(v.w, a1, d1[3]);
    }

    #pragma unroll 8
    for (int i = 4; i < CCH / 4; ++i) {
        int row = i * 4 + r4;
        float4 v = xp[(size_t)row * 72 + q];
        float a0 = a0s[row], a1 = a1s[row];
        s2[0] = fmaf(v.x, v.x, s2[0]); d0[0] = fmaf(v.x, a0, d0[0]); d1[0] = fmaf(v.x, a1, d1[0]);
        s2[1] = fmaf(v.y, v.y, s2[1]); d0[1] = fmaf(v.y, a0, d0[1]); d1[1] = fmaf(v.y, a1, d1[1]);
        s2[2] = fmaf(v.z, v.z, s2[2]); d0[2] = fmaf(v.z, a0, d0[2]); d1[2] = fmaf(v.z, a1, d1[2]);
        s2[3] = fmaf(v.w, v.w, s2[3]); d0[3] = fmaf(v.w, a0, d0[3]); d1[3] = fmaf(v.w, a1, d1[3]);
    }

    __shared__ float rs[4][72][12];
    float* dst = rs[r4][q];
    #pragma unroll
    for (int l = 0; l < 4; ++l) { dst[l] = s2[l]; dst[4+l] = d0[l]; dst[8+l] = d1[l]; }
    __syncthreads();

    if (r4 == 0) {
        float acc[12];
        #pragma unroll
        for (int j = 0; j < 12; ++j)
            acc[j] = rs[0][q][j] + rs[1][q][j] + rs[2][q][j] + rs[3][q][j];
        float* gp = g_part + (((size_t)b * NCH + ch) * 3) * HWs;
        #pragma unroll
        for (int j = 0; j < 3; ++j) {
            float4 o = make_float4(acc[4*j+0], acc[4*j+1], acc[4*j+2], acc[4*j+3]);
            *(float4*)(gp + (size_t)j * HWs + q * 4) = o;
        }
    }
}

// ---------------------------------------------------------------------------
// Kernel 2: anchor norms (inline) + reduce partials + 7 sinkhorn iterations,
// emit m and invden.  grid = B, block = 288.
// ---------------------------------------------------------------------------
__global__ void k_sinkhorn(const float* __restrict__ anchors,
                           float* __restrict__ out_m) {
    int b = blockIdx.x;
    int t = threadIdx.x;  // 0..287

    __shared__ float red0[16], red1[16];
    __shared__ float sc0, sc1;

    // ---- anchor inverse norms (reads are L2-hot; 64 concurrent blocks) ----
    {
        float n0 = 0.f, n1 = 0.f;
        for (int c = t; c < Cdim; c += 288) {
            float v = anchors[c];
            float w = anchors[Cdim + c];
            n0 = fmaf(v, v, n0);
            n1 = fmaf(w, w, n1);
        }
        #pragma unroll
        for (int o = 16; o; o >>= 1) {
            n0 += __shfl_down_sync(0xffffffffu, n0, o);
            n1 += __shfl_down_sync(0xffffffffu, n1, o);
        }
        if ((t & 31) == 0) { red0[t >> 5] = n0; red1[t >> 5] = n1; }
        __syncthreads();
        if (t < 32) {
            float q0 = (t < 9) ? red0[t] : 0.f;
            float q1 = (t < 9) ? red1[t] : 0.f;
            #pragma unroll
            for (int o = 8; o; o >>= 1) {
                q0 += __shfl_down_sync(0xffffffffu, q0, o);
                q1 += __shfl_down_sync(0xffffffffu, q1, o);
            }
            if (t == 0) {
                sc0 = 1.f / fmaxf(sqrtf(q0), 1e-12f);
                sc1 = 1.f / fmaxf(sqrtf(q1), 1e-12f);
            }
        }
        __syncthreads();
    }

    float s2 = 0.f, d0 = 0.f, d1 = 0.f;
    #pragma unroll
    for (int ch = 0; ch < NCH; ++ch) {
        const float* p = g_part + (((size_t)b * NCH + ch) * 3) * HWs;
        s2 += p[t];
        d0 += p[HWs + t];
        d1 += p[2 * HWs + t];
    }
    d0 *= sc0;   // apply deferred anchor normalization
    d1 *= sc1;
    float inorm = 1.f / fmaxf(sqrtf(s2), 1e-12f);
    const float ieps = 1.f / 0.07f;
    float K0 = expf(-(1.f - d0 * inorm) * ieps) + 1e-8f;
    float K1 = expf(-(1.f - d1 * inorm) * ieps) + 1e-8f;

    __shared__ float bc0, bc1;

    float v0 = 1.f, v1 = 1.f, u = 0.f;
    const float a = 1.f / (float)HWs;

    for (int it = 0; it < 7; ++it) {
        float Kv = K0 * v0 + K1 * v1 + 1e-8f;
        u = a / Kv;
        float r0 = K0 * u, r1 = K1 * u;
        #pragma unroll
        for (int o = 16; o; o >>= 1) {
            r0 += __shfl_down_sync(0xffffffffu, r0, o);
            r1 += __shfl_down_sync(0xffffffffu, r1, o);
        }
        if ((t & 31) == 0) { red0[t >> 5] = r0; red1[t >> 5] = r1; }
        __syncthreads();
        if (t < 32) {
            float q0 = (t < 9) ? red0[t] : 0.f;
            float q1 = (t < 9) ? red1[t] : 0.f;
            #pragma unroll
            for (int o = 8; o; o >>= 1) {
                q0 += __shfl_down_sync(0xffffffffu, q0, o);
                q1 += __shfl_down_sync(0xffffffffu, q1, o);
            }
            if (t == 0) { bc0 = 0.5f / (q0 + 1e-8f); bc1 = 0.5f / (q1 + 1e-8f); }
        }
        __syncthreads();
        v0 = bc0; v1 = bc1;
        __syncthreads();
    }

    float m0 = K0 * u * v0 * (float)HWs;
    float m1 = K1 * u * v1 * (float)HWs;
    float* om = out_m + (size_t)b * 2 * HWs;
    om[t]       = m0;
    om[HWs + t] = m1;

    float r0 = m0, r1 = m1;
    #pragma unroll
    for (int o = 16; o; o >>= 1) {
        r0 += __shfl_down_sync(0xffffffffu, r0, o);
        r1 += __shfl_down_sync(0xffffffffu, r1, o);
    }
    if ((t & 31) == 0) { red0[t >> 5] = r0; red1[t >> 5] = r1; }
    __syncthreads();
    if (t < 32) {
        float q0 = (t < 9) ? red0[t] : 0.f;
        float q1 = (t < 9) ? red1[t] : 0.f;
        #pragma unroll
        for (int o = 8; o; o >>= 1) {
            q0 += __shfl_down_sync(0xffffffffu, q0, o);
            q1 += __shfl_down_sync(0xffffffffu, q1, o);
        }
        if (t == 0) {
            g_invden[b * 2 + 0] = 1.f / (q0 + 1e-6f);
            g_invden[b * 2 + 1] = 1.f / (q1 + 1e-6f);
        }
    }
}

// ---------------------------------------------------------------------------
// Kernel 3: masked pooling (pass 2 over x).  grid = (C/64, B), block = 512.
// x LDGs issued BEFORE the m smem fill + barrier (overlap startup latency).
// m fill vectorized (float4).  invden read in epilogue.  (R12/13: 27.4us, 71.7%)
// ---------------------------------------------------------------------------
__global__ void k_pool(const float* __restrict__ x,
                       const float* __restrict__ m,
                       float* __restrict__ out) {
    int b  = blockIdx.y;
    int cg = blockIdx.x;
    int tid = threadIdx.x;  // 0..511

    int g = tid >> 3;        // channel within block (0..63)
    int q = tid & 7;         // quad slot (0..7)
    int c = cg * 64 + g;
    const float4* xp = (const float4*)(x + ((size_t)b * Cdim + c) * HWs);

    // 9 independent LDG.128 issued first — overlap the m fill + barrier below.
    float4 xv[9];
    #pragma unroll
    for (int j = 0; j < 9; ++j) xv[j] = xp[q + 8 * j];

    __shared__ float4 msv[144];
    const float4* mg = (const float4*)(m + (size_t)b * 2 * HWs);
    if (tid < 144) msv[tid] = mg[tid];
    __syncthreads();

    float s0a = 0.f, s0b = 0.f, s1a = 0.f, s1b = 0.f;
    #pragma unroll
    for (int j = 0; j < 9; ++j) {
        int i4 = q + 8 * j;
        float4 v  = xv[j];
        float4 w0 = msv[i4];
        float4 w1 = msv[72 + i4];
        s0a = fmaf(v.x, w0.x, s0a); s1a = fmaf(v.x, w1.x, s1a);
        s0b = fmaf(v.y, w0.y, s0b); s1b = fmaf(v.y, w1.y, s1b);
        s0a = fmaf(v.z, w0.z, s0a); s1a = fmaf(v.z, w1.z, s1a);
        s0b = fmaf(v.w, w0.w, s0b); s1b = fmaf(v.w, w1.w, s1b);
    }
    float s0 = s0a + s0b;
    float s1 = s1a + s1b;
    #pragma unroll
    for (int o = 4; o; o >>= 1) {
        s0 += __shfl_down_sync(0xffffffffu, s0, o, 8);
        s1 += __shfl_down_sync(0xffffffffu, s1, o, 8);
    }
    if (q == 0) {
        float i0 = g_invden[b * 2 + 0];
        float i1 = g_invden[b * 2 + 1];
        out[(size_t)b * Cdim + c]                      = s0 * i0;
        out[(size_t)Bsz * Cdim + (size_t)b * Cdim + c] = s1 * i1;
    }
}

// ---------------------------------------------------------------------------
extern "C" void kernel_launch(void* const* d_in, const int* in_sizes, int n_in,
                              void* d_out, int out_size) {
    const float* x       = (const float*)d_in[0];  // (64, 2048, 24, 12)
    const float* anchors = (const float*)d_in[1];  // (2, 2048)
    float* out = (float*)d_out;
    float* out_m = out + (size_t)2 * Bsz * Cdim;

    k_dots<<<dim3(Bsz, NCH), HWs>>>(x, anchors);
    k_sinkhorn<<<Bsz, HWs>>>(anchors, out_m);
    k_pool<<<dim3(Cdim / 64, Bsz), 512>>>(x, out_m, out);
}

// round 17
// speedup vs baseline: 1.1082x; 1.0081x over previous
#include <cuda_runtime.h>
#include <math.h>

#define Bsz 64
#define Cdim 2048
#define HWs 288
#define NCH 8
#define CCH (Cdim / NCH)   // 256 channels per k_dots block

// Scratch (no allocation allowed; __device__ globals)
__device__ float g_part[Bsz * NCH * 3 * HWs];       // partials, layout (b,ch,j,t)
__device__ float g_invden[Bsz * 2];                 // 1/(sum m + 1e-6)
__device__ int   g_cnt[Bsz];                        // per-batch arrival counters (zero-init)

// ---------------------------------------------------------------------------
// Kernel 1: dots (pass 1 over x) + LAST-CTA-per-batch sinkhorn tail.
// grid = (B, NCH=8), block = 288.  Streaming path identical to R16
// (raw anchors, deferred normalization, 4-row prefetch above the barrier).
// Only the last CTA of each batch (64/512) runs the sinkhorn epilogue.
// ---------------------------------------------------------------------------
__global__ void k_dots(const float* __restrict__ x,
                       const float* __restrict__ anchors,
                       float* __restrict__ out_m) {
    int b  = blockIdx.x;
    int ch = blockIdx.y;
    int t  = threadIdx.x;  // 0..287
    int r4 = t / 72;
    int q  = t % 72;

    const float4* xp = (const float4*)(x + ((size_t)b * Cdim + (size_t)ch * CCH) * HWs);

    // Prefetch rows r4, 4+r4, 8+r4, 12+r4 (independent of anchors) BEFORE barrier.
    float4 pf[4];
    #pragma unroll
    for (int l = 0; l < 4; ++l)
        pf[l] = xp[(size_t)(l * 4 + r4) * 72 + q];

    __shared__ float a0s[CCH], a1s[CCH];
    if (t < CCH) {
        a0s[t] = anchors[ch * CCH + t];            // raw (unnormalized)
        a1s[t] = anchors[Cdim + ch * CCH + t];
    }
    __syncthreads();

    float s2[4] = {0,0,0,0}, d0[4] = {0,0,0,0}, d1[4] = {0,0,0,0};

    // consume prefetched iterations i = 0..3
    #pragma unroll
    for (int l = 0; l < 4; ++l) {
        int row = l * 4 + r4;
        float4 v = pf[l];
        float a0 = a0s[row], a1 = a1s[row];
        s2[0] = fmaf(v.x, v.x, s2[0]); d0[0] = fmaf(v.x, a0, d0[0]); d1[0] = fmaf(v.x, a1, d1[0]);
        s2[1] = fmaf(v.y, v.y, s2[1]); d0[1] = fmaf(v.y, a0, d0[1]); d1[1] = fmaf(v.y, a1, d1[1]);
        s2[2] = fmaf(v.z, v.z, s2[2]); d0[2] = fmaf(v.z, a0, d0[2]); d1[2] = fmaf(v.z, a1, d1[2]);
        s2[3] = fmaf(v.w, v.w, s2[3]); d0[3] = fmaf(v.w, a0, d0[3]); d1[3] = fmaf(v.w, a1, d1[3]);
    }

    #pragma unroll 8
    for (int i = 4; i < CCH / 4; ++i) {
        int row = i * 4 + r4;
        float4 v = xp[(size_t)row * 72 + q];
        float a0 = a0s[row], a1 = a1s[row];
        s2[0] = fmaf(v.x, v.x, s2[0]); d0[0] = fmaf(v.x, a0, d0[0]); d1[0] = fmaf(v.x, a1, d1[0]);
        s2[1] = fmaf(v.y, v.y, s2[1]); d0[1] = fmaf(v.y, a0, d0[1]); d1[1] = fmaf(v.y, a1, d1[1]);
        s2[2] = fmaf(v.z, v.z, s2[2]); d0[2] = fmaf(v.z, a0, d0[2]); d1[2] = fmaf(v.z, a1, d1[2]);
        s2[3] = fmaf(v.w, v.w, s2[3]); d0[3] = fmaf(v.w, a0, d0[3]); d1[3] = fmaf(v.w, a1, d1[3]);
    }

    __shared__ float rs[4][72][12];
    float* dst = rs[r4][q];
    #pragma unroll
    for (int l = 0; l < 4; ++l) { dst[l] = s2[l]; dst[4+l] = d0[l]; dst[8+l] = d1[l]; }
    __syncthreads();

    if (r4 == 0) {
        float acc[12];
        #pragma unroll
        for (int j = 0; j < 12; ++j)
            acc[j] = rs[0][q][j] + rs[1][q][j] + rs[2][q][j] + rs[3][q][j];
        float* gp = g_part + (((size_t)b * NCH + ch) * 3) * HWs;
        #pragma unroll
        for (int j = 0; j < 3; ++j) {
            float4 o = make_float4(acc[4*j+0], acc[4*j+1], acc[4*j+2], acc[4*j+3]);
            *(float4*)(gp + (size_t)j * HWs + q * 4) = o;
        }
    }

    // ---- last-CTA-per-batch election (cheap for the other 7 CTAs) --------
    __threadfence();
    __syncthreads();
    __shared__ int s_last;
    if (t == 0) {
        int old = atomicAdd(&g_cnt[b], 1);
        s_last = (old == NCH - 1) ? 1 : 0;
    }
    __syncthreads();
    if (!s_last) return;
    __threadfence();

    // ================= sinkhorn tail (64 CTAs, one per batch) =============
    __shared__ float red0[16], red1[16];
    __shared__ float sc0, sc1;

    // anchor inverse norms (anchors L2-hot after the smem fills above)
    {
        float n0 = 0.f, n1 = 0.f;
        for (int c = t; c < Cdim; c += 288) {
            float v = anchors[c];
            float w = anchors[Cdim + c];
            n0 = fmaf(v, v, n0);
            n1 = fmaf(w, w, n1);
        }
        #pragma unroll
        for (int o = 16; o; o >>= 1) {
            n0 += __shfl_down_sync(0xffffffffu, n0, o);
            n1 += __shfl_down_sync(0xffffffffu, n1, o);
        }
        if ((t & 31) == 0) { red0[t >> 5] = n0; red1[t >> 5] = n1; }
        __syncthreads();
        if (t < 32) {
            float q0 = (t < 9) ? red0[t] : 0.f;
            float q1 = (t < 9) ? red1[t] : 0.f;
            #pragma unroll
            for (int o = 8; o; o >>= 1) {
                q0 += __shfl_down_sync(0xffffffffu, q0, o);
                q1 += __shfl_down_sync(0xffffffffu, q1, o);
            }
            if (t == 0) {
                sc0 = 1.f / fmaxf(sqrtf(q0), 1e-12f);
                sc1 = 1.f / fmaxf(sqrtf(q1), 1e-12f);
            }
        }
        __syncthreads();
    }

    float fs2 = 0.f, fd0 = 0.f, fd1 = 0.f;
    #pragma unroll
    for (int c2 = 0; c2 < NCH; ++c2) {
        const float* p = g_part + (((size_t)b * NCH + c2) * 3) * HWs;
        fs2 += __ldcg(p + t);
        fd0 += __ldcg(p + HWs + t);
        fd1 += __ldcg(p + 2 * HWs + t);
    }
    fd0 *= sc0;   // deferred anchor normalization
    fd1 *= sc1;
    float inorm = 1.f / fmaxf(sqrtf(fs2), 1e-12f);
    const float ieps = 1.f / 0.07f;
    float K0 = expf(-(1.f - fd0 * inorm) * ieps) + 1e-8f;
    float K1 = expf(-(1.f - fd1 * inorm) * ieps) + 1e-8f;

    __shared__ float bc0, bc1;
    float v0 = 1.f, v1 = 1.f, u = 0.f;
    const float a = 1.f / (float)HWs;

    for (int it = 0; it < 7; ++it) {
        float Kv = K0 * v0 + K1 * v1 + 1e-8f;
        u = a / Kv;
        float r0 = K0 * u, r1 = K1 * u;
        #pragma unroll
        for (int o = 16; o; o >>= 1) {
            r0 += __shfl_down_sync(0xffffffffu, r0, o);
            r1 += __shfl_down_sync(0xffffffffu, r1, o);
        }
        if ((t & 31) == 0) { red0[t >> 5] = r0; red1[t >> 5] = r1; }
        __syncthreads();
        if (t < 32) {
            float q0 = (t < 9) ? red0[t] : 0.f;
            float q1 = (t < 9) ? red1[t] : 0.f;
            #pragma unroll
            for (int o = 8; o; o >>= 1) {
                q0 += __shfl_down_sync(0xffffffffu, q0, o);
                q1 += __shfl_down_sync(0xffffffffu, q1, o);
            }
            if (t == 0) { bc0 = 0.5f / (q0 + 1e-8f); bc1 = 0.5f / (q1 + 1e-8f); }
        }
        __syncthreads();
        v0 = bc0; v1 = bc1;
        __syncthreads();
    }

    float m0 = K0 * u * v0 * (float)HWs;
    float m1 = K1 * u * v1 * (float)HWs;
    float* om = out_m + (size_t)b * 2 * HWs;
    om[t]       = m0;
    om[HWs + t] = m1;

    float r0 = m0, r1 = m1;
    #pragma unroll
    for (int o = 16; o; o >>= 1) {
        r0 += __shfl_down_sync(0xffffffffu, r0, o);
        r1 += __shfl_down_sync(0xffffffffu, r1, o);
    }
    if ((t & 31) == 0) { red0[t >> 5] = r0; red1[t >> 5] = r1; }
    __syncthreads();
    if (t < 32) {
        float q0 = (t < 9) ? red0[t] : 0.f;
        float q1 = (t < 9) ? red1[t] : 0.f;
        #pragma unroll
        for (int o = 8; o; o >>= 1) {
            q0 += __shfl_down_sync(0xffffffffu, q0, o);
            q1 += __shfl_down_sync(0xffffffffu, q1, o);
        }
        if (t == 0) {
            g_invden[b * 2 + 0] = 1.f / (q0 + 1e-6f);
            g_invden[b * 2 + 1] = 1.f / (q1 + 1e-6f);
            g_cnt[b] = 0;   // reset for next graph replay
        }
    }
}

// ---------------------------------------------------------------------------
// Kernel 2: masked pooling (pass 2 over x).  grid = (C/64, B), block = 512.
// x LDGs issued BEFORE the m smem fill + barrier (overlap startup latency).
// m fill vectorized (float4).  invden read in epilogue.  (R16: 27.4us, 71.7%)
// ---------------------------------------------------------------------------
__global__ void k_pool(const float* __restrict__ x,
                       const float* __restrict__ m,
                       float* __restrict__ out) {
    int b  = blockIdx.y;
    int cg = blockIdx.x;
    int tid = threadIdx.x;  // 0..511

    int g = tid >> 3;        // channel within block (0..63)
    int q = tid & 7;         // quad slot (0..7)
    int c = cg * 64 + g;
    const float4* xp = (const float4*)(x + ((size_t)b * Cdim + c) * HWs);

    // 9 independent LDG.128 issued first — overlap the m fill + barrier below.
    float4 xv[9];
    #pragma unroll
    for (int j = 0; j < 9; ++j) xv[j] = xp[q + 8 * j];

    __shared__ float4 msv[144];
    const float4* mg = (const float4*)(m + (size_t)b * 2 * HWs);
    if (tid < 144) msv[tid] = mg[tid];
    __syncthreads();

    float s0a = 0.f, s0b = 0.f, s1a = 0.f, s1b = 0.f;
    #pragma unroll
    for (int j = 0; j < 9; ++j) {
        int i4 = q + 8 * j;
        float4 v  = xv[j];
        float4 w0 = msv[i4];
        float4 w1 = msv[72 + i4];
        s0a = fmaf(v.x, w0.x, s0a); s1a = fmaf(v.x, w1.x, s1a);
        s0b = fmaf(v.y, w0.y, s0b); s1b = fmaf(v.y, w1.y, s1b);
        s0a = fmaf(v.z, w0.z, s0a); s1a = fmaf(v.z, w1.z, s1a);
        s0b = fmaf(v.w, w0.w, s0b); s1b = fmaf(v.w, w1.w, s1b);
    }
    float s0 = s0a + s0b;
    float s1 = s1a + s1b;
    #pragma unroll
    for (int o = 4; o; o >>= 1) {
        s0 += __shfl_down_sync(0xffffffffu, s0, o, 8);
        s1 += __shfl_down_sync(0xffffffffu, s1, o, 8);
    }
    if (q == 0) {
        float i0 = g_invden[b * 2 + 0];
        float i1 = g_invden[b * 2 + 1];
        out[(size_t)b * Cdim + c]                      = s0 * i0;
        out[(size_t)Bsz * Cdim + (size_t)b * Cdim + c] = s1 * i1;
    }
}

// ---------------------------------------------------------------------------
extern "C" void kernel_launch(void* const* d_in, const int* in_sizes, int n_in,
                              void* d_out, int out_size) {
    const float* x       = (const float*)d_in[0];  // (64, 2048, 24, 12)
    const float* anchors = (const float*)d_in[1];  // (2, 2048)
    float* out = (float*)d_out;
    float* out_m = out + (size_t)2 * Bsz * Cdim;

    k_dots<<<dim3(Bsz, NCH), HWs>>>(x, anchors, out_m);
    k_pool<<<dim3(Cdim / 64, Bsz), 512>>>(x, out_m, out);
}